// round 12
// baseline (speedup 1.0000x reference)
#include <cuda_runtime.h>
#include <cuda_bf16.h>

#define NATOMS 512
#define NBATCH 16
#define NP 16

// ---- compile-time constants (constexpr repeated-multiply; NO runtime pow) ----
constexpr double RQd = 0.09913776814937592;   // exp(-2*eta*dshf^2)
constexpr double rqp(int n) {
    double r = 1.0;
    for (int i = 0; i < n; ++i) r *= RQd;
    return r;
}
constexpr float RQ4_1 = (float)rqp(4),  RQ4_2 = (float)rqp(8),  RQ4_3 = (float)rqp(12);
constexpr float T1_0  = (float)rqp(1),  T1_1  = (float)rqp(9),
                T1_2  = (float)rqp(17), T1_3  = (float)rqp(25);
constexpr float T2_0  = (float)rqp(3),  T2_1  = (float)rqp(11),
                T2_2  = (float)rqp(19), T2_3  = (float)rqp(27);

// exp(-16*sp^2) for sp = 0.9 + 0.26875*p : diagonal (d==0) correction terms
__constant__ float DIAG[16] = {
    2.3525e-6f, 3.1654e-10f, 4.3761e-15f, 5.8930e-21f,
    7.8650e-28f, 1.0413e-35f, 1.3600e-44f, 0.0f,
    0.0f, 0.0f, 0.0f, 0.0f, 0.0f, 0.0f, 0.0f, 0.0f};

__global__ void __launch_bounds__(256, 7) aev_radial_kernel(
    const float* __restrict__ dmat,   // [B, N, N]
    const float* __restrict__ zall,   // [B, N]
    float* __restrict__ out)          // [B, N, 16]
{
    constexpr float RCR       = 5.2f;
    constexpr float PI_OVER_R = 3.14159265358979323846f / 5.2f;
    constexpr double L2E = 1.4426950408889634;
    constexpr double ETA = 16.0, DSH = 0.26875;
    constexpr float  C2  = (float)(-ETA * L2E);             // -eta*log2e
    constexpr float  A1  = (float)( 2.0 * ETA * DSH * L2E); //  2*eta*dshf*log2e
    constexpr float  A0  = (float)(-ETA * DSH * DSH * L2E); // -eta*dshf^2*log2e
    constexpr float  GSP = 1.075f;                          // 4*dshf

    const int warp_g = (blockIdx.x * blockDim.x + threadIdx.x) >> 5;  // 0..8191
    const int lane   = threadIdx.x & 31;
    const int b      = warp_g >> 9;          // batch 0..15
    const int i      = warp_g & 511;         // row within batch

    const float* __restrict__ row  = dmat + (size_t)warp_g * NATOMS;
    const float* __restrict__ zrow = zall + (size_t)b * NATOMS;
    const unsigned FULL = 0xffffffffu;

    float acc[NP];
#pragma unroll
    for (int p = 0; p < NP; ++p) acc[p] = 0.0f;

#pragma unroll
    for (int it = 0; it < 4; ++it) {
        const int j0 = it * 128 + lane * 4;
        const float4 dv = *reinterpret_cast<const float4*>(row  + j0);
        const float4 zv = *reinterpret_cast<const float4*>(zrow + j0);
        const float dd[4] = {dv.x, dv.y, dv.z, dv.w};
        const float zz[4] = {zv.x, zv.y, zv.z, zv.w};

#pragma unroll
        for (int e = 0; e < 4; ++e) {
            // clamp once; fc(clamped) ~ 0 for d>=RCR (cos(pi) = -1), so no
            // compare/select is needed. Diagonal d==0 is included here and
            // subtracted exactly after the reduction.
            const float dg = fminf(dd[e], RCR);
            float c;
            asm("cos.approx.ftz.f32 %0, %1;" : "=f"(c) : "f"(dg * PI_OVER_R));
            const float hz = 0.5f * zz[e];
            const float w  = fmaf(hz, c, hz);          // z*(0.5*cos+0.5)

            const float u0 = dg - 0.9f;
            float q;
            asm("ex2.approx.ftz.f32 %0, %1;" : "=f"(q) : "f"(fmaf(A1, u0, A0)));
            const float s = q * q;                      // bounded: dg <= RCR

            float g0, v1, v2, v3;
            // k = 0
            asm("ex2.approx.ftz.f32 %0, %1;" : "=f"(g0) : "f"((C2 * u0) * u0));
            v1 = g0 * q;
            v2 = g0 * (s * T1_0);
            v3 = v1 * (s * T2_0);
            acc[0] = fmaf(w, g0, acc[0]);
            acc[1] = fmaf(w, v1, acc[1]);
            acc[2] = fmaf(w, v2, acc[2]);
            acc[3] = fmaf(w, v3, acc[3]);
            // k = 1
            {
                const float uk = u0 - GSP;
                asm("ex2.approx.ftz.f32 %0, %1;" : "=f"(g0) : "f"((C2 * uk) * uk));
                v1 = g0 * (q * RQ4_1);
                v2 = g0 * (s * T1_1);
                v3 = v1 * (s * T2_1);
                acc[4] = fmaf(w, g0, acc[4]);
                acc[5] = fmaf(w, v1, acc[5]);
                acc[6] = fmaf(w, v2, acc[6]);
                acc[7] = fmaf(w, v3, acc[7]);
            }
            // k = 2
            {
                const float uk = u0 - 2.0f * GSP;
                asm("ex2.approx.ftz.f32 %0, %1;" : "=f"(g0) : "f"((C2 * uk) * uk));
                v1 = g0 * (q * RQ4_2);
                v2 = g0 * (s * T1_2);
                v3 = v1 * (s * T2_2);
                acc[8]  = fmaf(w, g0, acc[8]);
                acc[9]  = fmaf(w, v1, acc[9]);
                acc[10] = fmaf(w, v2, acc[10]);
                acc[11] = fmaf(w, v3, acc[11]);
            }
            // k = 3
            {
                const float uk = u0 - 3.0f * GSP;
                asm("ex2.approx.ftz.f32 %0, %1;" : "=f"(g0) : "f"((C2 * uk) * uk));
                v1 = g0 * (q * RQ4_3);
                v2 = g0 * (s * T1_3);
                v3 = v1 * (s * T2_3);
                acc[12] = fmaf(w, g0, acc[12]);
                acc[13] = fmaf(w, v1, acc[13]);
                acc[14] = fmaf(w, v2, acc[14]);
                acc[15] = fmaf(w, v3, acc[15]);
            }
        }
    }

    // halving reduction in place: 16 regs -> 1 reg across 32 lanes
#pragma unroll
    for (int v = 0; v < 8; ++v) {
        const bool hi = (lane & 16);
        const float send = hi ? acc[v] : acc[v + 8];
        const float r = __shfl_xor_sync(FULL, send, 16);
        acc[v] = (hi ? acc[v + 8] : acc[v]) + r;
    }
#pragma unroll
    for (int v = 0; v < 4; ++v) {
        const bool hi = (lane & 8);
        const float send = hi ? acc[v] : acc[v + 4];
        const float r = __shfl_xor_sync(FULL, send, 8);
        acc[v] = (hi ? acc[v + 4] : acc[v]) + r;
    }
#pragma unroll
    for (int v = 0; v < 2; ++v) {
        const bool hi = (lane & 4);
        const float send = hi ? acc[v] : acc[v + 2];
        const float r = __shfl_xor_sync(FULL, send, 4);
        acc[v] = (hi ? acc[v + 2] : acc[v]) + r;
    }
    {
        const bool hi = (lane & 2);
        const float send = hi ? acc[0] : acc[1];
        const float r = __shfl_xor_sync(FULL, send, 2);
        acc[0] = (hi ? acc[1] : acc[0]) + r;
    }
    acc[0] += __shfl_xor_sync(FULL, acc[0], 1);

    if ((lane & 1) == 0) {
        const int f  = (lane >> 1) & 15;
        const float zi = zrow[i];                     // L1-hot
        out[(size_t)warp_g * NP + f] = fmaf(-zi, DIAG[f], acc[0]);
    }
}

extern "C" void kernel_launch(void* const* d_in, const int* in_sizes, int n_in,
                              void* d_out, int out_size)
{
    const float* dmat = (const float*)d_in[0];   // [16, 512, 512] float32
    const float* zall = (const float*)d_in[1];   // [16, 512] float32
    float* out        = (float*)d_out;           // [16, 512, 16] float32

    // 1024 blocks x 256 threads = 8192 warps, one row per warp.
    // launch_bounds(256,7) caps regs at 36 -> 7 CTAs/SM -> 56 warps/SM,
    // single balanced wave (1024 CTAs / 148 SMs = 6.9).
    aev_radial_kernel<<<1024, 256>>>(dmat, zall, out);
}

// round 13
// speedup vs baseline: 1.1382x; 1.1382x over previous
#include <cuda_runtime.h>
#include <cuda_bf16.h>

#define NATOMS 512
#define NBATCH 16
#define NP 16

// ---- compile-time constants (constexpr repeated-multiply; NO runtime pow) ----
constexpr double RQd = 0.09913776814937592;   // exp(-2*eta*dshf^2)
constexpr double rqp(int n) {
    double r = 1.0;
    for (int i = 0; i < n; ++i) r *= RQd;
    return r;
}
constexpr double L2Ed = 1.4426950408889634;
constexpr double ETAd = 16.0, DSHd = 0.26875;
constexpr double C2d  = -ETAd * L2Ed;                    // -eta*log2e

// q_k = q * RQ^{4k};  g2/g0 = s*RQ^{8k+1};  g3/g1 = s*RQ^{8k+3}
constexpr float RQ4_1 = (float)rqp(4),  RQ4_2 = (float)rqp(8),  RQ4_3 = (float)rqp(12);
constexpr float T1_0  = (float)rqp(1),  T1_1  = (float)rqp(9),
                T1_2  = (float)rqp(17), T1_3  = (float)rqp(25);
constexpr float T2_0  = (float)rqp(3),  T2_1  = (float)rqp(11),
                T2_2  = (float)rqp(19), T2_3  = (float)rqp(27);
// incremental ex2-arg: arg_k = fma(TC_k, u0, arg0) + DD_k
constexpr float TC_1 = (float)(-8.0 * C2d * DSHd * 1.0);
constexpr float TC_2 = (float)(-8.0 * C2d * DSHd * 2.0);
constexpr float TC_3 = (float)(-8.0 * C2d * DSHd * 3.0);
constexpr float DD_1 = (float)(16.0 * C2d * DSHd * DSHd * 1.0);
constexpr float DD_2 = (float)(16.0 * C2d * DSHd * DSHd * 4.0);
constexpr float DD_3 = (float)(16.0 * C2d * DSHd * DSHd * 9.0);

// exp(-16*sp^2), sp = 0.9 + 0.26875*p : diagonal (d==0) correction terms
__constant__ float DIAG[16] = {
    2.3525e-6f, 3.1654e-10f, 4.3761e-15f, 5.8930e-21f,
    7.8650e-28f, 1.0413e-35f, 1.3600e-44f, 0.0f,
    0.0f, 0.0f, 0.0f, 0.0f, 0.0f, 0.0f, 0.0f, 0.0f};

__global__ void __launch_bounds__(128) aev_radial_kernel(
    const float* __restrict__ dmat,   // [B, N, N]
    const float* __restrict__ zall,   // [B, N]
    float* __restrict__ out)          // [B, N, 16]
{
    constexpr float RCR       = 5.2f;
    constexpr float PI_OVER_R = 3.14159265358979323846f / 5.2f;
    constexpr float C2  = (float)C2d;
    constexpr float A1  = (float)( 2.0 * ETAd * DSHd * L2Ed);
    constexpr float A0  = (float)(-ETAd * DSHd * DSHd * L2Ed);

    const int warp_g = (blockIdx.x * blockDim.x + threadIdx.x) >> 5;  // 0..4095
    const int lane   = threadIdx.x & 31;
    const int b      = warp_g >> 8;          // batch 0..15
    const int i0     = warp_g & 255;         // base row within batch

    const float* __restrict__ zrow = zall + (size_t)b * NATOMS;
    const unsigned FULL = 0xffffffffu;

    // each warp computes two rows: i0 and i0+256 (same batch -> shared z row)
#pragma unroll 1
    for (int half = 0; half < 2; ++half) {
        const int wg = b * NATOMS + i0 + half * 256;
        const float* __restrict__ row = dmat + (size_t)wg * NATOMS;

        float acc[NP];
#pragma unroll
        for (int p = 0; p < NP; ++p) acc[p] = 0.0f;

#pragma unroll
        for (int it = 0; it < 4; ++it) {
            const int j0 = it * 128 + lane * 4;
            const float4 dv = *reinterpret_cast<const float4*>(row  + j0);
            const float4 zv = *reinterpret_cast<const float4*>(zrow + j0);
            const float dd[4] = {dv.x, dv.y, dv.z, dv.w};
            const float zz[4] = {zv.x, zv.y, zv.z, zv.w};

#pragma unroll
            for (int e = 0; e < 4; ++e) {
                // clamp once; fc(clamped) ~ 0 for d>=RCR, no compare needed.
                // diagonal d==0 subtracted exactly at the store.
                const float dg = fminf(dd[e], RCR);
                float c;
                asm("cos.approx.ftz.f32 %0, %1;" : "=f"(c) : "f"(dg * PI_OVER_R));
                // w' = z*(cos+1); the 0.5 of fc is applied at the store
                const float w = fmaf(zz[e], c, zz[e]);

                const float u0 = dg - 0.9f;
                float q;
                asm("ex2.approx.ftz.f32 %0, %1;" : "=f"(q) : "f"(fmaf(A1, u0, A0)));
                const float s    = q * q;            // bounded: dg <= RCR
                const float c2u  = C2 * u0;
                const float arg0 = c2u * u0;

                float g, G, GQ;
                // k = 0
                asm("ex2.approx.ftz.f32 %0, %1;" : "=f"(g) : "f"(arg0));
                G  = w * g;
                GQ = G * q;
                acc[0] += G;
                acc[1]  = fmaf(G,  q,        acc[1]);
                acc[2]  = fmaf(G,  s * T1_0, acc[2]);
                acc[3]  = fmaf(GQ, s * T2_0, acc[3]);
                // k = 1
                {
                    const float arg = fmaf(TC_1, u0, arg0) + DD_1;
                    asm("ex2.approx.ftz.f32 %0, %1;" : "=f"(g) : "f"(arg));
                    const float qk = q * RQ4_1;
                    G  = w * g;
                    GQ = G * qk;
                    acc[4] += G;
                    acc[5]  = fmaf(G,  qk,       acc[5]);
                    acc[6]  = fmaf(G,  s * T1_1, acc[6]);
                    acc[7]  = fmaf(GQ, s * T2_1, acc[7]);
                }
                // k = 2
                {
                    const float arg = fmaf(TC_2, u0, arg0) + DD_2;
                    asm("ex2.approx.ftz.f32 %0, %1;" : "=f"(g) : "f"(arg));
                    const float qk = q * RQ4_2;
                    G  = w * g;
                    GQ = G * qk;
                    acc[8]  += G;
                    acc[9]   = fmaf(G,  qk,       acc[9]);
                    acc[10]  = fmaf(G,  s * T1_2, acc[10]);
                    acc[11]  = fmaf(GQ, s * T2_2, acc[11]);
                }
                // k = 3
                {
                    const float arg = fmaf(TC_3, u0, arg0) + DD_3;
                    asm("ex2.approx.ftz.f32 %0, %1;" : "=f"(g) : "f"(arg));
                    const float qk = q * RQ4_3;
                    G  = w * g;
                    GQ = G * qk;
                    acc[12] += G;
                    acc[13]  = fmaf(G,  qk,       acc[13]);
                    acc[14]  = fmaf(G,  s * T1_3, acc[14]);
                    acc[15]  = fmaf(GQ, s * T2_3, acc[15]);
                }
            }
        }

        // halving reduction in place: 16 regs -> 1 reg across 32 lanes
#pragma unroll
        for (int v = 0; v < 8; ++v) {
            const bool hi = (lane & 16);
            const float send = hi ? acc[v] : acc[v + 8];
            const float r = __shfl_xor_sync(FULL, send, 16);
            acc[v] = (hi ? acc[v + 8] : acc[v]) + r;
        }
#pragma unroll
        for (int v = 0; v < 4; ++v) {
            const bool hi = (lane & 8);
            const float send = hi ? acc[v] : acc[v + 4];
            const float r = __shfl_xor_sync(FULL, send, 8);
            acc[v] = (hi ? acc[v + 4] : acc[v]) + r;
        }
#pragma unroll
        for (int v = 0; v < 2; ++v) {
            const bool hi = (lane & 4);
            const float send = hi ? acc[v] : acc[v + 2];
            const float r = __shfl_xor_sync(FULL, send, 4);
            acc[v] = (hi ? acc[v + 2] : acc[v]) + r;
        }
        {
            const bool hi = (lane & 2);
            const float send = hi ? acc[0] : acc[1];
            const float r = __shfl_xor_sync(FULL, send, 2);
            acc[0] = (hi ? acc[1] : acc[0]) + r;
        }
        acc[0] += __shfl_xor_sync(FULL, acc[0], 1);

        if ((lane & 1) == 0) {
            const int f  = (lane >> 1) & 15;
            const float zi = zrow[i0 + half * 256];          // L1-hot
            // apply the deferred 0.5 and subtract the exact diagonal term
            out[(size_t)wg * NP + f] = fmaf(0.5f, acc[0], -zi * DIAG[f]);
        }
    }
}

extern "C" void kernel_launch(void* const* d_in, const int* in_sizes, int n_in,
                              void* d_out, int out_size)
{
    const float* dmat = (const float*)d_in[0];   // [16, 512, 512] float32
    const float* zall = (const float*)d_in[1];   // [16, 512] float32
    float* out        = (float*)d_out;           // [16, 512, 16] float32

    // 1024 blocks x 128 threads = 4096 warps; each warp does 2 rows.
    // Single balanced wave, natural register allocation (no cap).
    aev_radial_kernel<<<1024, 128>>>(dmat, zall, out);
}